// round 3
// baseline (speedup 1.0000x reference)
#include <cuda_runtime.h>
#include <math.h>

#define EPS 1e-8f

// Each thread processes VEC float4s (front-batched loads for MLP).
#define VEC 2
#define THREADS 256
#define F4_PER_BLOCK (THREADS * VEC)

__device__ __forceinline__ float fuse_op(float x, float y,
                                         float w0, float w1, float w2,
                                         float w3, float w4, float w5) {
    float ax = fabsf(x);
    float ay = fabsf(y);
    float sy = __sinf(y);
    float sx = __sinf(x);
    float d1 = __fdividef(x, ay + EPS);
    float d2 = __fdividef(y, ax + EPS);
    float r = w0 * (x + y);
    r = fmaf(w1, x * y, r);
    r = fmaf(w2, d1, r);
    r = fmaf(w3, d2, r);
    r = fmaf(w4, x * sy, r);
    r = fmaf(w5, y * sx, r);
    return r;
}

// Warp-0 prologue: softmax over op axis per column j (16 columns), sum over j.
// Result broadcast to the block via smem. Cost ~300 cycles, hidden by other CTAs.
__device__ __forceinline__ void compute_weights_block(const float* __restrict__ param,
                                                      float* sw, int tid) {
    if (tid < 32) {
        float c0 = 0.f, c1 = 0.f, c2 = 0.f, c3 = 0.f, c4 = 0.f, c5 = 0.f;
        if (tid < 16) {
            float v0 = __ldg(&param[0 * 16 + tid]);
            float v1 = __ldg(&param[1 * 16 + tid]);
            float v2 = __ldg(&param[2 * 16 + tid]);
            float v3 = __ldg(&param[3 * 16 + tid]);
            float v4 = __ldg(&param[4 * 16 + tid]);
            float v5 = __ldg(&param[5 * 16 + tid]);
            float m = fmaxf(fmaxf(fmaxf(v0, v1), fmaxf(v2, v3)), fmaxf(v4, v5));
            float e0 = __expf(v0 - m), e1 = __expf(v1 - m), e2 = __expf(v2 - m);
            float e3 = __expf(v3 - m), e4 = __expf(v4 - m), e5 = __expf(v5 - m);
            float s = ((e0 + e1) + (e2 + e3)) + (e4 + e5);
            float inv = 1.0f / s;
            c0 = e0 * inv; c1 = e1 * inv; c2 = e2 * inv;
            c3 = e3 * inv; c4 = e4 * inv; c5 = e5 * inv;
        }
        #pragma unroll
        for (int off = 16; off > 0; off >>= 1) {
            c0 += __shfl_xor_sync(0xFFFFFFFFu, c0, off);
            c1 += __shfl_xor_sync(0xFFFFFFFFu, c1, off);
            c2 += __shfl_xor_sync(0xFFFFFFFFu, c2, off);
            c3 += __shfl_xor_sync(0xFFFFFFFFu, c3, off);
            c4 += __shfl_xor_sync(0xFFFFFFFFu, c4, off);
            c5 += __shfl_xor_sync(0xFFFFFFFFu, c5, off);
        }
        if (tid == 0) {
            sw[0] = c0; sw[1] = c1; sw[2] = c2;
            sw[3] = c3; sw[4] = c4; sw[5] = c5;
        }
    }
    __syncthreads();
}

__global__ void __launch_bounds__(THREADS)
fused_elementwise_kernel(const float4* __restrict__ x4,
                         const float4* __restrict__ y4,
                         float4* __restrict__ out4,
                         long long n4,
                         const float* __restrict__ param) {
    __shared__ float sw[6];
    int tid = threadIdx.x;
    compute_weights_block(param, sw, tid);

    float w0 = sw[0], w1 = sw[1], w2 = sw[2];
    float w3 = sw[3], w4 = sw[4], w5 = sw[5];

    long long base = (long long)blockIdx.x * F4_PER_BLOCK + tid;
    long long i0 = base;
    long long i1 = base + THREADS;

    bool v0 = (i0 < n4);
    bool v1 = (i1 < n4);

    // Front-batched streaming loads: 4 independent LDG.128 in flight.
    float4 xa, ya, xb, yb;
    if (v0) { xa = __ldcs(&x4[i0]); ya = __ldcs(&y4[i0]); }
    if (v1) { xb = __ldcs(&x4[i1]); yb = __ldcs(&y4[i1]); }

    if (v0) {
        float4 o;
        o.x = fuse_op(xa.x, ya.x, w0, w1, w2, w3, w4, w5);
        o.y = fuse_op(xa.y, ya.y, w0, w1, w2, w3, w4, w5);
        o.z = fuse_op(xa.z, ya.z, w0, w1, w2, w3, w4, w5);
        o.w = fuse_op(xa.w, ya.w, w0, w1, w2, w3, w4, w5);
        __stcs(&out4[i0], o);
    }
    if (v1) {
        float4 o;
        o.x = fuse_op(xb.x, yb.x, w0, w1, w2, w3, w4, w5);
        o.y = fuse_op(xb.y, yb.y, w0, w1, w2, w3, w4, w5);
        o.z = fuse_op(xb.z, yb.z, w0, w1, w2, w3, w4, w5);
        o.w = fuse_op(xb.w, yb.w, w0, w1, w2, w3, w4, w5);
        __stcs(&out4[i1], o);
    }
}

// Scalar tail (n % 4 != 0 — not expected for this shape, but safe).
__global__ void fused_tail_kernel(const float* __restrict__ x,
                                  const float* __restrict__ y,
                                  float* __restrict__ out,
                                  long long start, long long n,
                                  const float* __restrict__ param) {
    __shared__ float sw[6];
    compute_weights_block(param, sw, (int)threadIdx.x);
    long long idx = start + (long long)blockIdx.x * blockDim.x + threadIdx.x;
    if (idx >= n) return;
    out[idx] = fuse_op(x[idx], y[idx], sw[0], sw[1], sw[2], sw[3], sw[4], sw[5]);
}

extern "C" void kernel_launch(void* const* d_in, const int* in_sizes, int n_in,
                              void* d_out, int out_size) {
    const float* x = (const float*)d_in[0];
    const float* y = (const float*)d_in[1];
    const float* param = (const float*)d_in[2];
    float* out = (float*)d_out;

    long long n = (long long)in_sizes[0];  // 4*4096*4096 = 67108864
    long long n4 = n / 4;
    long long tail_start = n4 * 4;

    long long blocks = (n4 + F4_PER_BLOCK - 1) / F4_PER_BLOCK;
    fused_elementwise_kernel<<<(unsigned)blocks, THREADS>>>(
        (const float4*)x, (const float4*)y, (float4*)out, n4, param);

    if (tail_start < n) {
        long long tail = n - tail_start;
        long long tblocks = (tail + 255) / 256;
        fused_tail_kernel<<<(unsigned)tblocks, 256>>>(x, y, out, tail_start, n, param);
    }
}